// round 3
// baseline (speedup 1.0000x reference)
#include <cuda_runtime.h>
#include <cstdint>

#define SEQ   2048
#define DH    128
#define BQ    64
#define BK    64
#define NBH   64           // B*H = 4*16
#define KPAD  132          // K smem row stride (floats): (8nb+g)*132 + 8s+tg -> banks 4g+tg, conflict-free
#define VPAD  136          // V smem row stride (floats): (8kb+tg)*136 + 8db+g -> banks 8tg+g, conflict-free
#define PPAD  68           // P smem row stride (floats): g*68 + 8kb+tg -> banks 4g+tg, conflict-free
// smem layout (floats): Ks[64*132] | Vs[64*136] | Ps[4 warps][16][68]
#define KS_OFF 0
#define VS_OFF (64 * KPAD)
#define PS_OFF (VS_OFF + 64 * VPAD)
#define SMEM_FLOATS (PS_OFF + 4 * 16 * PPAD)
#define SMEM_BYTES (SMEM_FLOATS * 4)   // 86016 B -> 2 CTAs/SM can co-reside

__device__ __forceinline__ float tf32r(float x) {
    uint32_t u;
    asm("cvt.rna.tf32.f32 %0, %1;" : "=r"(u) : "f"(x));
    return __uint_as_float(u);
}
__device__ __forceinline__ uint32_t tf32u(float x) {
    uint32_t u;
    asm("cvt.rna.tf32.f32 %0, %1;" : "=r"(u) : "f"(x));
    return u;
}

__device__ __forceinline__ void mma_tf32(float c[4],
                                         uint32_t a0, uint32_t a1, uint32_t a2, uint32_t a3,
                                         uint32_t b0, uint32_t b1) {
    asm volatile(
        "mma.sync.aligned.m16n8k8.row.col.f32.tf32.tf32.f32 "
        "{%0,%1,%2,%3}, {%4,%5,%6,%7}, {%8,%9}, {%0,%1,%2,%3};"
        : "+f"(c[0]), "+f"(c[1]), "+f"(c[2]), "+f"(c[3])
        : "r"(a0), "r"(a1), "r"(a2), "r"(a3), "r"(b0), "r"(b1));
}

__global__ void __launch_bounds__(128)
fa_tf32_kernel(const float* __restrict__ q, const float* __restrict__ k,
               const float* __restrict__ v, const float* __restrict__ mask,
               float* __restrict__ out) {
    extern __shared__ float smem[];
    float* Ks = smem + KS_OFF;
    float* Vs = smem + VS_OFF;

    const int tid  = threadIdx.x;
    const int warp = tid >> 5;
    const int lane = tid & 31;
    const int g    = lane >> 2;   // group id (row within m16)
    const int tg   = lane & 3;    // thread-in-group

    float* Ps = smem + PS_OFF + warp * (16 * PPAD);

    const int qt = blockIdx.x;    // q tile (0..31)
    const int bh = blockIdx.y;    // flattened (b,h)
    const int q0 = qt * BQ;
    const size_t base = (size_t)bh * SEQ * DH;

    // ---- Q fragments (tf32, pre-scaled), resident in regs: 16 k-steps x 4 regs ----
    const float scale = 0.08838834764831845f;   // 1/sqrt(128)
    const float* qp = q + base + (size_t)(q0 + warp * 16) * DH;
    uint32_t qa[16][4];
#pragma unroll
    for (int s = 0; s < 16; s++) {
        qa[s][0] = tf32u(qp[(size_t)g       * DH + 8 * s + tg    ] * scale);
        qa[s][1] = tf32u(qp[(size_t)(g + 8) * DH + 8 * s + tg    ] * scale);
        qa[s][2] = tf32u(qp[(size_t)g       * DH + 8 * s + tg + 4] * scale);
        qa[s][3] = tf32u(qp[(size_t)(g + 8) * DH + 8 * s + tg + 4] * scale);
    }

    float oacc[16][4];
#pragma unroll
    for (int d = 0; d < 16; d++) {
        oacc[d][0] = 0.f; oacc[d][1] = 0.f; oacc[d][2] = 0.f; oacc[d][3] = 0.f;
    }
    float mrow0 = -1e30f, mrow1 = -1e30f;
    float lrow0 = 0.f,    lrow1 = 0.f;

    const float* mk0 = mask + (size_t)(q0 + warp * 16 + g)     * SEQ;
    const float* mk1 = mask + (size_t)(q0 + warp * 16 + g + 8) * SEQ;

    for (int kt = 0; kt < SEQ / BK; kt++) {
        __syncthreads();   // previous iteration done reading Ks/Vs
        // ---- cooperative load K,V tiles (tf32-rounded at store) ----
        const float4* kg4 = (const float4*)(k + base + (size_t)kt * BK * DH);
        const float4* vg4 = (const float4*)(v + base + (size_t)kt * BK * DH);
#pragma unroll
        for (int it = 0; it < 16; it++) {
            int idx = tid + it * 128;          // 0..2047 (64 rows x 32 float4)
            int n = idx >> 5, c = idx & 31;
            float4 a = kg4[idx];
            float4 b = vg4[idx];
            a.x = tf32r(a.x); a.y = tf32r(a.y); a.z = tf32r(a.z); a.w = tf32r(a.w);
            b.x = tf32r(b.x); b.y = tf32r(b.y); b.z = tf32r(b.z); b.w = tf32r(b.w);
            *(float4*)(Ks + n * KPAD + 4 * c) = a;
            *(float4*)(Vs + n * VPAD + 4 * c) = b;
        }
        __syncthreads();

        // ---- S = Q K^T (16x64 per warp), fp32 accum ----
        float sacc[8][4];
#pragma unroll
        for (int nb = 0; nb < 8; nb++) {
            sacc[nb][0] = 0.f; sacc[nb][1] = 0.f; sacc[nb][2] = 0.f; sacc[nb][3] = 0.f;
        }
#pragma unroll
        for (int s = 0; s < 16; s++) {
#pragma unroll
            for (int nb = 0; nb < 8; nb++) {
                const float* kr = Ks + (8 * nb + g) * KPAD + 8 * s + tg;
                uint32_t b0 = __float_as_uint(kr[0]);
                uint32_t b1 = __float_as_uint(kr[4]);
                mma_tf32(sacc[nb], qa[s][0], qa[s][1], qa[s][2], qa[s][3], b0, b1);
            }
        }

        // ---- add mask, online softmax ----
        const float* mt0 = mk0 + kt * BK;
        const float* mt1 = mk1 + kt * BK;
        float tmax0 = -1e30f, tmax1 = -1e30f;
#pragma unroll
        for (int nb = 0; nb < 8; nb++) {
            float2 m0 = *(const float2*)(mt0 + 8 * nb + 2 * tg);
            float2 m1 = *(const float2*)(mt1 + 8 * nb + 2 * tg);
            sacc[nb][0] += m0.x; sacc[nb][1] += m0.y;
            sacc[nb][2] += m1.x; sacc[nb][3] += m1.y;
            tmax0 = fmaxf(tmax0, fmaxf(sacc[nb][0], sacc[nb][1]));
            tmax1 = fmaxf(tmax1, fmaxf(sacc[nb][2], sacc[nb][3]));
        }
        tmax0 = fmaxf(tmax0, __shfl_xor_sync(0xffffffffu, tmax0, 1));
        tmax0 = fmaxf(tmax0, __shfl_xor_sync(0xffffffffu, tmax0, 2));
        tmax1 = fmaxf(tmax1, __shfl_xor_sync(0xffffffffu, tmax1, 1));
        tmax1 = fmaxf(tmax1, __shfl_xor_sync(0xffffffffu, tmax1, 2));

        float mnew0 = fmaxf(mrow0, tmax0);
        float mnew1 = fmaxf(mrow1, tmax1);
        float corr0 = __expf(mrow0 - mnew0);
        float corr1 = __expf(mrow1 - mnew1);

        float rsum0 = 0.f, rsum1 = 0.f;
#pragma unroll
        for (int nb = 0; nb < 8; nb++) {
            float p0 = __expf(sacc[nb][0] - mnew0);
            float p1 = __expf(sacc[nb][1] - mnew0);
            float p2 = __expf(sacc[nb][2] - mnew1);
            float p3 = __expf(sacc[nb][3] - mnew1);
            rsum0 += p0 + p1;
            rsum1 += p2 + p3;
            Ps[g * PPAD + 8 * nb + 2 * tg]           = tf32r(p0);
            Ps[g * PPAD + 8 * nb + 2 * tg + 1]       = tf32r(p1);
            Ps[(g + 8) * PPAD + 8 * nb + 2 * tg]     = tf32r(p2);
            Ps[(g + 8) * PPAD + 8 * nb + 2 * tg + 1] = tf32r(p3);
        }
        rsum0 += __shfl_xor_sync(0xffffffffu, rsum0, 1);
        rsum0 += __shfl_xor_sync(0xffffffffu, rsum0, 2);
        rsum1 += __shfl_xor_sync(0xffffffffu, rsum1, 1);
        rsum1 += __shfl_xor_sync(0xffffffffu, rsum1, 2);
        lrow0 = lrow0 * corr0 + rsum0;
        lrow1 = lrow1 * corr1 + rsum1;
        mrow0 = mnew0;
        mrow1 = mnew1;

        // rescale O accumulators
#pragma unroll
        for (int db = 0; db < 16; db++) {
            oacc[db][0] *= corr0; oacc[db][1] *= corr0;
            oacc[db][2] *= corr1; oacc[db][3] *= corr1;
        }

        __syncwarp();   // P stores visible to the warp's A-fragment reads

        // ---- O += P V (k = 64 keys, n = 128 dims) ----
#pragma unroll
        for (int kb = 0; kb < 8; kb++) {
            uint32_t a0 = __float_as_uint(Ps[g * PPAD + 8 * kb + tg]);
            uint32_t a1 = __float_as_uint(Ps[(g + 8) * PPAD + 8 * kb + tg]);
            uint32_t a2 = __float_as_uint(Ps[g * PPAD + 8 * kb + tg + 4]);
            uint32_t a3 = __float_as_uint(Ps[(g + 8) * PPAD + 8 * kb + tg + 4]);
#pragma unroll
            for (int db = 0; db < 16; db++) {
                uint32_t b0 = __float_as_uint(Vs[(8 * kb + tg)     * VPAD + 8 * db + g]);
                uint32_t b1 = __float_as_uint(Vs[(8 * kb + tg + 4) * VPAD + 8 * db + g]);
                mma_tf32(oacc[db], a0, a1, a2, a3, b0, b1);
            }
        }
    }

    // ---- epilogue: O / l -> gmem ----
    float inv0 = 1.0f / lrow0;
    float inv1 = 1.0f / lrow1;
    float* op = out + base + (size_t)(q0 + warp * 16) * DH;
#pragma unroll
    for (int db = 0; db < 16; db++) {
        int c = 8 * db + 2 * tg;
        *(float2*)(op + (size_t)g       * DH + c) = make_float2(oacc[db][0] * inv0, oacc[db][1] * inv0);
        *(float2*)(op + (size_t)(g + 8) * DH + c) = make_float2(oacc[db][2] * inv1, oacc[db][3] * inv1);
    }
}

extern "C" void kernel_launch(void* const* d_in, const int* in_sizes, int n_in,
                              void* d_out, int out_size) {
    const float* q    = (const float*)d_in[0];
    const float* k    = (const float*)d_in[1];
    const float* v    = (const float*)d_in[2];
    const float* mask = (const float*)d_in[3];
    float* out = (float*)d_out;

    cudaFuncSetAttribute(fa_tf32_kernel,
                         cudaFuncAttributeMaxDynamicSharedMemorySize, SMEM_BYTES);

    dim3 grid(SEQ / BQ, NBH);   // (32, 64)
    fa_tf32_kernel<<<grid, 128, SMEM_BYTES>>>(q, k, v, mask, out);
}